// round 1
// baseline (speedup 1.0000x reference)
#include <cuda_runtime.h>
#include <cuda_bf16.h>
#include <math.h>

// Problem constants (fixed by the dataset):
//   features [N=2, C=256, H=200, W=200] f32
//   rois     [R=512, 5] f32  (batch, x1, y1, x2, y2)
//   masks    [R=512, MH=128, MW=128] f32
//   out      [R, C, 7, 7] f32
#define C_CH   256
#define FH     200
#define FW     200
#define MH     128
#define MW     128
#define OUT_HW 7
#define NSAMP  196        // 14 x 14 sample points per roi
#define SCALE  0.25f

__global__ __launch_bounds__(256, 4)
void roialign_kernel(const float* __restrict__ feat,
                     const float* __restrict__ rois,
                     const float* __restrict__ masks,
                     float* __restrict__ out)
{
    __shared__ int   s_o00[NSAMP], s_o01[NSAMP], s_o10[NSAMP], s_o11[NSAMP];
    __shared__ float s_w00[NSAMP], s_w01[NSAMP], s_w10[NSAMP], s_w11[NSAMP];

    const int r = blockIdx.x;
    const int t = threadIdx.x;

    // ---- roi params (broadcast loads) ----
    const float* roi = rois + (size_t)r * 5;
    const int   b   = (int)roi[0];
    const float rx1 = roi[1], ry1 = roi[2], rx2 = roi[3], ry2 = roi[4];

    const float rsw = rx1 * SCALE;
    const float rsh = ry1 * SCALE;
    const float rw  = fmaxf((rx2 - rx1 + 1.0f) * SCALE, 1.0f);
    const float rh  = fmaxf((ry2 - ry1 + 1.0f) * SCALE, 1.0f);
    const float bw  = rw * (1.0f / 7.0f);
    const float bh  = rh * (1.0f / 7.0f);

    // ---- phase 1: per-sample bilinear corners + combined (mask * bilerp) weights ----
    if (t < NSAMP) {
        const int iy = t / 14;
        const int ix = t - iy * 14;
        // sample coord: start + (bin + (sub+0.5)/2)*binsz = start + (i*0.5+0.25)*binsz
        const float y = rsh + ((float)iy * 0.5f + 0.25f) * bh;
        const float x = rsw + ((float)ix * 0.5f + 0.25f) * bw;

        const bool valid = (y > -1.0f) && (y < (float)FH) &&
                           (x > -1.0f) && (x < (float)FW);

        const float yc = fminf(fmaxf(y, 0.0f), (float)(FH - 1));
        const float xc = fminf(fmaxf(x, 0.0f), (float)(FW - 1));
        const int y0 = (int)floorf(yc);
        const int x0 = (int)floorf(xc);
        const int y1i = min(y0 + 1, FH - 1);
        const int x1i = min(x0 + 1, FW - 1);
        const float ly = yc - (float)y0;
        const float lx = xc - (float)x0;
        const float hy = 1.0f - ly;
        const float hx = 1.0f - lx;

        // mask weight at same sample point, roi-relative image coords
        const float my = fminf(fmaxf(y * 4.0f - ry1, 0.0f), ry2 - ry1);
        const float mx = fminf(fmaxf(x * 4.0f - rx1, 0.0f), rx2 - rx1);
        const int  my0 = (int)floorf(my);
        const int  mx0 = (int)floorf(mx);
        const int  my1 = min(my0 + 1, MH - 1);
        const int  mx1 = min(mx0 + 1, MW - 1);
        const float lmy = my - (float)my0;
        const float lmx = mx - (float)mx0;
        const float hmy = 1.0f - lmy;
        const float hmx = 1.0f - lmx;

        const float* mp = masks + (size_t)r * (MH * MW);
        const float wgt = hmy * hmx * __ldg(mp + my0 * MW + mx0)
                        + hmy * lmx * __ldg(mp + my0 * MW + mx1)
                        + lmy * hmx * __ldg(mp + my1 * MW + mx0)
                        + lmy * lmx * __ldg(mp + my1 * MW + mx1);

        const float wv = valid ? wgt : 0.0f;

        s_o00[t] = y0  * FW + x0;
        s_o01[t] = y0  * FW + x1i;
        s_o10[t] = y1i * FW + x0;
        s_o11[t] = y1i * FW + x1i;
        s_w00[t] = wv * hy * hx;
        s_w01[t] = wv * hy * lx;
        s_w10[t] = wv * ly * hx;
        s_w11[t] = wv * ly * lx;
    }
    __syncthreads();

    // ---- phase 2: gather + weighted sum. warp -> channel, lane -> bin ----
    const int warp = t >> 5;
    const int lane = t & 31;

    // each lane owns bins {lane, lane+32}; hoist sample indices out of channel loop
    const int binA = lane;
    const int byA  = binA / 7;
    const int bxA  = binA - byA * 7;
    const int sA   = byA * 28 + bxA * 2;   // (byA*2)*14 + bxA*2

    const int binB = lane + 32;
    const bool hasB = (binB < 49);
    const int byB  = binB / 7;
    const int bxB  = binB - byB * 7;
    const int sB   = byB * 28 + bxB * 2;

    auto samp = [&](const float* __restrict__ fp, int si) -> float {
        return fmaf(s_w00[si], __ldg(fp + s_o00[si]),
               fmaf(s_w01[si], __ldg(fp + s_o01[si]),
               fmaf(s_w10[si], __ldg(fp + s_o10[si]),
                    s_w11[si] * __ldg(fp + s_o11[si]))));
    };

    const size_t fbase = (size_t)b * C_CH * (FH * FW);
    const size_t obase = (size_t)r * C_CH * 49;

    for (int c = warp; c < C_CH; c += 8) {
        const float* fp = feat + fbase + (size_t)c * (FH * FW);
        float* op = out + obase + (size_t)c * 49;

        float accA = samp(fp, sA) + samp(fp, sA + 1)
                   + samp(fp, sA + 14) + samp(fp, sA + 15);
        op[binA] = accA * 0.25f;

        if (hasB) {
            float accB = samp(fp, sB) + samp(fp, sB + 1)
                       + samp(fp, sB + 14) + samp(fp, sB + 15);
            op[binB] = accB * 0.25f;
        }
    }
}

extern "C" void kernel_launch(void* const* d_in, const int* in_sizes, int n_in,
                              void* d_out, int out_size)
{
    const float* feat  = (const float*)d_in[0];
    const float* rois  = (const float*)d_in[1];
    const float* masks = (const float*)d_in[2];
    float* out = (float*)d_out;

    const int R = in_sizes[1] / 5;   // 512
    roialign_kernel<<<R, 256>>>(feat, rois, masks, out);
}

// round 3
// speedup vs baseline: 1.3441x; 1.3441x over previous
#include <cuda_runtime.h>
#include <cuda_bf16.h>
#include <math.h>

// features [N=2, C=256, H=200, W=200] f32  (NCHW input)
// rois     [R=512, 5] f32
// masks    [R=512, 128, 128] f32
// out      [R, 256, 7, 7] f32
#define NIMG  2
#define C_CH  256
#define FH    200
#define FW    200
#define PIX   (FH * FW)
#define MH    128
#define MW    128
#define NSAMP 196
#define SCALE 0.25f
#define OTILE_LD 132   // 128 channels (one half) padded to 132

// NHWC-transposed features scratch: 2*40000*256 floats = 81.92 MB
__device__ float g_ft[(size_t)NIMG * PIX * C_CH];

// ---------------- NCHW -> NHWC transpose ----------------
// per image: 2D transpose of [C=256, P=40000] -> [P, C]
__global__ __launch_bounds__(256)
void transpose_kernel(const float* __restrict__ feat)
{
    __shared__ float tile[32][33];
    const int p0  = blockIdx.x * 32;
    const int c0  = blockIdx.y * 32;
    const int img = blockIdx.z;
    const int tx = threadIdx.x;   // 0..31
    const int ty = threadIdx.y;   // 0..7

    const float* in = feat + ((size_t)img * C_CH) * PIX;
#pragma unroll
    for (int k = 0; k < 4; ++k) {
        const int c = c0 + ty + k * 8;
        tile[ty + k * 8][tx] = in[(size_t)c * PIX + p0 + tx];
    }
    __syncthreads();
    float* outp = g_ft + ((size_t)img * PIX) * C_CH;
#pragma unroll
    for (int k = 0; k < 4; ++k) {
        const int p = p0 + ty + k * 8;
        outp[(size_t)p * C_CH + c0 + tx] = tile[tx][ty + k * 8];
    }
}

// ---------------- mask-weighted RoIAlign on NHWC features ----------------
__global__ __launch_bounds__(256)
void roialign_kernel(const float* __restrict__ rois,
                     const float* __restrict__ masks,
                     float* __restrict__ out)
{
    __shared__ int   s_o00[NSAMP], s_o01[NSAMP], s_o10[NSAMP], s_o11[NSAMP];
    __shared__ float s_w00[NSAMP], s_w01[NSAMP], s_w10[NSAMP], s_w11[NSAMP];
    __shared__ float s_out[49 * OTILE_LD];

    const int r = blockIdx.x;
    const int t = threadIdx.x;

    const float* roi = rois + (size_t)r * 5;
    const int   b   = (int)roi[0];
    const float rx1 = roi[1], ry1 = roi[2], rx2 = roi[3], ry2 = roi[4];

    const float rsw = rx1 * SCALE;
    const float rsh = ry1 * SCALE;
    const float rw  = fmaxf((rx2 - rx1 + 1.0f) * SCALE, 1.0f);
    const float rh  = fmaxf((ry2 - ry1 + 1.0f) * SCALE, 1.0f);
    const float bw  = rw * (1.0f / 7.0f);
    const float bh  = rh * (1.0f / 7.0f);

    // ---- phase 1: per-sample corner offsets (NHWC element offsets) + weights ----
    if (t < NSAMP) {
        const int iy = t / 14;
        const int ix = t - iy * 14;
        const float y = rsh + ((float)iy * 0.5f + 0.25f) * bh;
        const float x = rsw + ((float)ix * 0.5f + 0.25f) * bw;

        const bool valid = (y > -1.0f) && (y < (float)FH) &&
                           (x > -1.0f) && (x < (float)FW);

        const float yc = fminf(fmaxf(y, 0.0f), (float)(FH - 1));
        const float xc = fminf(fmaxf(x, 0.0f), (float)(FW - 1));
        const int y0  = (int)floorf(yc);
        const int x0  = (int)floorf(xc);
        const int y1i = min(y0 + 1, FH - 1);
        const int x1i = min(x0 + 1, FW - 1);
        const float ly = yc - (float)y0;
        const float lx = xc - (float)x0;
        const float hy = 1.0f - ly;
        const float hx = 1.0f - lx;

        const float my = fminf(fmaxf(y * 4.0f - ry1, 0.0f), ry2 - ry1);
        const float mx = fminf(fmaxf(x * 4.0f - rx1, 0.0f), rx2 - rx1);
        const int  my0 = (int)floorf(my);
        const int  mx0 = (int)floorf(mx);
        const int  my1 = min(my0 + 1, MH - 1);
        const int  mx1 = min(mx0 + 1, MW - 1);
        const float lmy = my - (float)my0;
        const float lmx = mx - (float)mx0;
        const float hmy = 1.0f - lmy;
        const float hmx = 1.0f - lmx;

        const float* mp = masks + (size_t)r * (MH * MW);
        const float wgt = hmy * hmx * __ldg(mp + my0 * MW + mx0)
                        + hmy * lmx * __ldg(mp + my0 * MW + mx1)
                        + lmy * hmx * __ldg(mp + my1 * MW + mx0)
                        + lmy * lmx * __ldg(mp + my1 * MW + mx1);

        const float wv = valid ? wgt : 0.0f;

        const int base = b * PIX;                    // pixel base for this image
        s_o00[t] = (base + y0  * FW + x0 ) * C_CH;
        s_o01[t] = (base + y0  * FW + x1i) * C_CH;
        s_o10[t] = (base + y1i * FW + x0 ) * C_CH;
        s_o11[t] = (base + y1i * FW + x1i) * C_CH;
        s_w00[t] = wv * hy * hx;
        s_w01[t] = wv * hy * lx;
        s_w10[t] = wv * ly * hx;
        s_w11[t] = wv * ly * lx;
    }
    __syncthreads();

    // ---- phase 2: lanes = channels (float4 each), warp sweeps bins ----
    const int warp = t >> 5;
    const int lane = t & 31;
    const float* __restrict__ ft = g_ft;

#pragma unroll
    for (int half = 0; half < 2; ++half) {
        const int c = half * 128 + lane * 4;

        for (int bin = warp; bin < 49; bin += 8) {
            const int by = bin / 7;
            const int bx = bin - by * 7;
            const int s0 = by * 28 + bx * 2;

            float4 acc = make_float4(0.f, 0.f, 0.f, 0.f);
#pragma unroll
            for (int j = 0; j < 4; ++j) {
                const int si = s0 + ((j >> 1) * 14) + (j & 1);
                const float w0 = s_w00[si];
                const float w1 = s_w01[si];
                const float w2 = s_w10[si];
                const float w3 = s_w11[si];
                const float4 v0 = __ldg((const float4*)(ft + s_o00[si] + c));
                const float4 v1 = __ldg((const float4*)(ft + s_o01[si] + c));
                const float4 v2 = __ldg((const float4*)(ft + s_o10[si] + c));
                const float4 v3 = __ldg((const float4*)(ft + s_o11[si] + c));
                acc.x = fmaf(w0, v0.x, fmaf(w1, v1.x, fmaf(w2, v2.x, fmaf(w3, v3.x, acc.x))));
                acc.y = fmaf(w0, v0.y, fmaf(w1, v1.y, fmaf(w2, v2.y, fmaf(w3, v3.y, acc.y))));
                acc.z = fmaf(w0, v0.z, fmaf(w1, v1.z, fmaf(w2, v2.z, fmaf(w3, v3.z, acc.z))));
                acc.w = fmaf(w0, v0.w, fmaf(w1, v1.w, fmaf(w2, v2.w, fmaf(w3, v3.w, acc.w))));
            }
            acc.x *= 0.25f; acc.y *= 0.25f; acc.z *= 0.25f; acc.w *= 0.25f;
            *(float4*)&s_out[bin * OTILE_LD + lane * 4] = acc;
        }
        __syncthreads();

        // coalesced store of this channel-half: out[r][half*128+cc][bin]
        float* op = out + ((size_t)r * C_CH + half * 128) * 49;
        for (int cc = warp; cc < 128; cc += 8)
            for (int k = lane; k < 49; k += 32)
                op[cc * 49 + k] = s_out[k * OTILE_LD + cc];
        __syncthreads();
    }
}

extern "C" void kernel_launch(void* const* d_in, const int* in_sizes, int n_in,
                              void* d_out, int out_size)
{
    const float* feat  = (const float*)d_in[0];
    const float* rois  = (const float*)d_in[1];
    const float* masks = (const float*)d_in[2];
    float* out = (float*)d_out;

    const int R = in_sizes[1] / 5;   // 512

    dim3 tgrid(PIX / 32, C_CH / 32, NIMG);   // 1250 x 8 x 2
    dim3 tblk(32, 8);
    transpose_kernel<<<tgrid, tblk>>>(feat);

    roialign_kernel<<<R, 256>>>(rois, masks, out);
}

// round 6
// speedup vs baseline: 1.7931x; 1.3341x over previous
#include <cuda_runtime.h>
#include <cuda_fp16.h>
#include <math.h>

// features [N=2, C=256, H=200, W=200] f32  (NCHW input)
// rois     [R=512, 5] f32
// masks    [R=512, 128, 128] f32
// out      [R, 256, 7, 7] f32
#define NIMG  2
#define C_CH  256
#define FH    200
#define FW    200
#define PIX   (FH * FW)
#define MH    128
#define MW    128
#define NSAMP 196
#define SCALE 0.25f
#define OTILE_LD 132   // 128 channels (one half) padded

// NHWC fp16 feature copy: 2*40000*256 halves = 40.96 MB
__device__ __half g_fth[(size_t)NIMG * PIX * C_CH];

// ---------------- NCHW f32 -> NHWC f16 transpose ----------------
// tile: 64 channels x 32 pixels. Reads 128B/warp, writes 128B/warp (__half2).
__global__ __launch_bounds__(256)
void transpose_kernel(const float* __restrict__ feat)
{
    __shared__ float tile[32][65];        // [pixel][channel]
    const int p0  = blockIdx.x * 32;
    const int c0  = blockIdx.y * 64;
    const int img = blockIdx.z;
    const int tx = threadIdx.x;           // 0..31
    const int ty = threadIdx.y;           // 0..7

    const float* in = feat + (size_t)img * C_CH * PIX;
#pragma unroll
    for (int k = 0; k < 8; ++k) {
        const int c = ty + k * 8;         // 0..63
        tile[tx][c] = in[(size_t)(c0 + c) * PIX + p0 + tx];
    }
    __syncthreads();

    __half* outp = g_fth + (size_t)img * PIX * C_CH;
#pragma unroll
    for (int k = 0; k < 4; ++k) {
        const int p = ty + k * 8;         // 0..31
        const float v0 = tile[p][2 * tx];
        const float v1 = tile[p][2 * tx + 1];
        const __half2 h = __floats2half2_rn(v0, v1);
        *(__half2*)(outp + (size_t)(p0 + p) * C_CH + c0 + 2 * tx) = h;
    }
}

// ---------------- mask-weighted RoIAlign on NHWC f16 features ----------------
__device__ __forceinline__ float4 h4f(uint2 u)
{
    const __half2 lo = *reinterpret_cast<const __half2*>(&u.x);
    const __half2 hi = *reinterpret_cast<const __half2*>(&u.y);
    const float2 a = __half22float2(lo);
    const float2 b = __half22float2(hi);
    return make_float4(a.x, a.y, b.x, b.y);
}

__global__ __launch_bounds__(256)
void roialign_kernel(const float* __restrict__ rois,
                     const float* __restrict__ masks,
                     float* __restrict__ out)
{
    __shared__ int   s_o00[NSAMP], s_o01[NSAMP], s_o10[NSAMP], s_o11[NSAMP];
    __shared__ float s_w00[NSAMP], s_w01[NSAMP], s_w10[NSAMP], s_w11[NSAMP];
    __shared__ float s_out[49 * OTILE_LD];

    const int r = blockIdx.x;
    const int t = threadIdx.x;

    const float* roi = rois + (size_t)r * 5;
    const int   b   = (int)roi[0];
    const float rx1 = roi[1], ry1 = roi[2], rx2 = roi[3], ry2 = roi[4];

    const float rsw = rx1 * SCALE;
    const float rsh = ry1 * SCALE;
    const float rw  = fmaxf((rx2 - rx1 + 1.0f) * SCALE, 1.0f);
    const float rh  = fmaxf((ry2 - ry1 + 1.0f) * SCALE, 1.0f);
    const float bw  = rw * (1.0f / 7.0f);
    const float bh  = rh * (1.0f / 7.0f);

    // ---- phase 1: per-sample corner offsets (half-element indices) + weights ----
    if (t < NSAMP) {
        const int iy = t / 14;
        const int ix = t - iy * 14;
        const float y = rsh + ((float)iy * 0.5f + 0.25f) * bh;
        const float x = rsw + ((float)ix * 0.5f + 0.25f) * bw;

        const bool valid = (y > -1.0f) && (y < (float)FH) &&
                           (x > -1.0f) && (x < (float)FW);

        const float yc = fminf(fmaxf(y, 0.0f), (float)(FH - 1));
        const float xc = fminf(fmaxf(x, 0.0f), (float)(FW - 1));
        const int y0  = (int)floorf(yc);
        const int x0  = (int)floorf(xc);
        const int y1i = min(y0 + 1, FH - 1);
        const int x1i = min(x0 + 1, FW - 1);
        const float ly = yc - (float)y0;
        const float lx = xc - (float)x0;
        const float hy = 1.0f - ly;
        const float hx = 1.0f - lx;

        const float my = fminf(fmaxf(y * 4.0f - ry1, 0.0f), ry2 - ry1);
        const float mx = fminf(fmaxf(x * 4.0f - rx1, 0.0f), rx2 - rx1);
        const int  my0 = (int)floorf(my);
        const int  mx0 = (int)floorf(mx);
        const int  my1 = min(my0 + 1, MH - 1);
        const int  mx1 = min(mx0 + 1, MW - 1);
        const float lmy = my - (float)my0;
        const float lmx = mx - (float)mx0;
        const float hmy = 1.0f - lmy;
        const float hmx = 1.0f - lmx;

        const float* mp = masks + (size_t)r * (MH * MW);
        const float wgt = hmy * hmx * __ldg(mp + my0 * MW + mx0)
                        + hmy * lmx * __ldg(mp + my0 * MW + mx1)
                        + lmy * hmx * __ldg(mp + my1 * MW + mx0)
                        + lmy * lmx * __ldg(mp + my1 * MW + mx1);

        const float wv = valid ? wgt : 0.0f;

        const int base = b * PIX;
        s_o00[t] = (base + y0  * FW + x0 ) * C_CH;
        s_o01[t] = (base + y0  * FW + x1i) * C_CH;
        s_o10[t] = (base + y1i * FW + x0 ) * C_CH;
        s_o11[t] = (base + y1i * FW + x1i) * C_CH;
        s_w00[t] = wv * hy * hx;
        s_w01[t] = wv * hy * lx;
        s_w10[t] = wv * ly * hx;
        s_w11[t] = wv * ly * lx;
    }
    __syncthreads();

    // ---- phase 2: lanes = 4 channels each (LDG.64 of halves), warp sweeps bins ----
    const int warp = t >> 5;
    const int lane = t & 31;
    const __half* __restrict__ ft = g_fth;

#pragma unroll
    for (int half = 0; half < 2; ++half) {
        const int c = half * 128 + lane * 4;

        for (int bin = warp; bin < 49; bin += 8) {
            const int by = bin / 7;
            const int bx = bin - by * 7;
            const int s0 = by * 28 + bx * 2;

            float4 acc = make_float4(0.f, 0.f, 0.f, 0.f);
#pragma unroll
            for (int j = 0; j < 4; ++j) {
                const int si = s0 + ((j >> 1) * 14) + (j & 1);
                const float w0 = s_w00[si];
                const float w1 = s_w01[si];
                const float w2 = s_w10[si];
                const float w3 = s_w11[si];
                const float4 v0 = h4f(__ldg((const uint2*)(ft + s_o00[si] + c)));
                const float4 v1 = h4f(__ldg((const uint2*)(ft + s_o01[si] + c)));
                const float4 v2 = h4f(__ldg((const uint2*)(ft + s_o10[si] + c)));
                const float4 v3 = h4f(__ldg((const uint2*)(ft + s_o11[si] + c)));
                acc.x = fmaf(w0, v0.x, fmaf(w1, v1.x, fmaf(w2, v2.x, fmaf(w3, v3.x, acc.x))));
                acc.y = fmaf(w0, v0.y, fmaf(w1, v1.y, fmaf(w2, v2.y, fmaf(w3, v3.y, acc.y))));
                acc.z = fmaf(w0, v0.z, fmaf(w1, v1.z, fmaf(w2, v2.z, fmaf(w3, v3.z, acc.z))));
                acc.w = fmaf(w0, v0.w, fmaf(w1, v1.w, fmaf(w2, v2.w, fmaf(w3, v3.w, acc.w))));
            }
            acc.x *= 0.25f; acc.y *= 0.25f; acc.z *= 0.25f; acc.w *= 0.25f;
            *(float4*)&s_out[bin * OTILE_LD + lane * 4] = acc;
        }
        __syncthreads();

        float* op = out + ((size_t)r * C_CH + half * 128) * 49;
        for (int cc = warp; cc < 128; cc += 8)
            for (int k = lane; k < 49; k += 32)
                op[cc * 49 + k] = s_out[k * OTILE_LD + cc];
        __syncthreads();
    }
}

extern "C" void kernel_launch(void* const* d_in, const int* in_sizes, int n_in,
                              void* d_out, int out_size)
{
    const float* feat  = (const float*)d_in[0];
    const float* rois  = (const float*)d_in[1];
    const float* masks = (const float*)d_in[2];
    float* out = (float*)d_out;

    const int R = in_sizes[1] / 5;   // 512

    dim3 tgrid(PIX / 32, C_CH / 64, NIMG);   // 1250 x 4 x 2
    dim3 tblk(32, 8);
    transpose_kernel<<<tgrid, tblk>>>(feat);

    roialign_kernel<<<R, 256>>>(rois, masks, out);
}

// round 9
// speedup vs baseline: 2.0094x; 1.1206x over previous
#include <cuda_runtime.h>
#include <cuda_fp16.h>
#include <math.h>

// features [N=2, C=256, H=200, W=200] f32  (NCHW input)
// rois     [R=512, 5] f32
// masks    [R=512, 128, 128] f32
// out      [R, 256, 7, 7] f32
#define NIMG  2
#define C_CH  256
#define FH    200
#define FW    200
#define PIX   (FH * FW)
#define MH    128
#define MW    128
#define NSAMP 196
#define SCALE 0.25f
#define SOUT_LD 264   // 256 channels + 8 pad (16B-multiple rows)

// NHWC fp16 feature copy: 2*40000*256 halves = 40.96 MB
__device__ __align__(16) __half g_fth[(size_t)NIMG * PIX * C_CH];

// ---------------- NCHW f32 -> NHWC f16 transpose (unchanged from R6) ----------------
__global__ __launch_bounds__(256)
void transpose_kernel(const float* __restrict__ feat)
{
    __shared__ float tile[32][65];        // [pixel][channel]
    const int p0  = blockIdx.x * 32;
    const int c0  = blockIdx.y * 64;
    const int img = blockIdx.z;
    const int tx = threadIdx.x;           // 0..31
    const int ty = threadIdx.y;           // 0..7

    const float* in = feat + (size_t)img * C_CH * PIX;
#pragma unroll
    for (int k = 0; k < 8; ++k) {
        const int c = ty + k * 8;         // 0..63
        tile[tx][c] = in[(size_t)(c0 + c) * PIX + p0 + tx];
    }
    __syncthreads();

    __half* outp = g_fth + (size_t)img * PIX * C_CH;
#pragma unroll
    for (int k = 0; k < 4; ++k) {
        const int p = ty + k * 8;         // 0..31
        const float v0 = tile[p][2 * tx];
        const float v1 = tile[p][2 * tx + 1];
        const __half2 h = __floats2half2_rn(v0, v1);
        *(__half2*)(outp + (size_t)(p0 + p) * C_CH + c0 + 2 * tx) = h;
    }
}

// ---------------- mask-weighted RoIAlign on NHWC f16 features ----------------
// uint4 = 8 halves; accumulate weighted into 8 f32 accumulators
__device__ __forceinline__ void acc8(float acc[8], uint4 u, float w)
{
    float2 f;
    f = __half22float2(*reinterpret_cast<__half2*>(&u.x));
    acc[0] = fmaf(w, f.x, acc[0]); acc[1] = fmaf(w, f.y, acc[1]);
    f = __half22float2(*reinterpret_cast<__half2*>(&u.y));
    acc[2] = fmaf(w, f.x, acc[2]); acc[3] = fmaf(w, f.y, acc[3]);
    f = __half22float2(*reinterpret_cast<__half2*>(&u.z));
    acc[4] = fmaf(w, f.x, acc[4]); acc[5] = fmaf(w, f.y, acc[5]);
    f = __half22float2(*reinterpret_cast<__half2*>(&u.w));
    acc[6] = fmaf(w, f.x, acc[6]); acc[7] = fmaf(w, f.y, acc[7]);
}

__global__ __launch_bounds__(256)
void roialign_kernel(const float* __restrict__ rois,
                     const float* __restrict__ masks,
                     float* __restrict__ out)
{
    __shared__ int   s_o00[NSAMP], s_o01[NSAMP], s_o10[NSAMP], s_o11[NSAMP];
    __shared__ float s_w00[NSAMP], s_w01[NSAMP], s_w10[NSAMP], s_w11[NSAMP];
    __shared__ float s_out[25 * SOUT_LD];     // <= 25 bins per block

    const int r = blockIdx.x;
    const int t = threadIdx.x;

    const float* roi = rois + (size_t)r * 5;
    const int   b   = (int)roi[0];
    const float rx1 = roi[1], ry1 = roi[2], rx2 = roi[3], ry2 = roi[4];

    const float rsw = rx1 * SCALE;
    const float rsh = ry1 * SCALE;
    const float rw  = fmaxf((rx2 - rx1 + 1.0f) * SCALE, 1.0f);
    const float rh  = fmaxf((ry2 - ry1 + 1.0f) * SCALE, 1.0f);
    const float bw  = rw * (1.0f / 7.0f);
    const float bh  = rh * (1.0f / 7.0f);

    // ---- phase 1: per-sample corner offsets (half-element indices) + weights ----
    if (t < NSAMP) {
        const int iy = t / 14;
        const int ix = t - iy * 14;
        const float y = rsh + ((float)iy * 0.5f + 0.25f) * bh;
        const float x = rsw + ((float)ix * 0.5f + 0.25f) * bw;

        const bool valid = (y > -1.0f) && (y < (float)FH) &&
                           (x > -1.0f) && (x < (float)FW);

        const float yc = fminf(fmaxf(y, 0.0f), (float)(FH - 1));
        const float xc = fminf(fmaxf(x, 0.0f), (float)(FW - 1));
        const int y0  = (int)floorf(yc);
        const int x0  = (int)floorf(xc);
        const int y1i = min(y0 + 1, FH - 1);
        const int x1i = min(x0 + 1, FW - 1);
        const float ly = yc - (float)y0;
        const float lx = xc - (float)x0;
        const float hy = 1.0f - ly;
        const float hx = 1.0f - lx;

        const float my = fminf(fmaxf(y * 4.0f - ry1, 0.0f), ry2 - ry1);
        const float mx = fminf(fmaxf(x * 4.0f - rx1, 0.0f), rx2 - rx1);
        const int  my0 = (int)floorf(my);
        const int  mx0 = (int)floorf(mx);
        const int  my1 = min(my0 + 1, MH - 1);
        const int  mx1 = min(mx0 + 1, MW - 1);
        const float lmy = my - (float)my0;
        const float lmx = mx - (float)mx0;
        const float hmy = 1.0f - lmy;
        const float hmx = 1.0f - lmx;

        const float* mp = masks + (size_t)r * (MH * MW);
        const float wgt = hmy * hmx * __ldg(mp + my0 * MW + mx0)
                        + hmy * lmx * __ldg(mp + my0 * MW + mx1)
                        + lmy * hmx * __ldg(mp + my1 * MW + mx0)
                        + lmy * lmx * __ldg(mp + my1 * MW + mx1);

        const float wv = valid ? wgt : 0.0f;

        const int base = b * PIX;
        s_o00[t] = (base + y0  * FW + x0 ) * C_CH;
        s_o01[t] = (base + y0  * FW + x1i) * C_CH;
        s_o10[t] = (base + y1i * FW + x0 ) * C_CH;
        s_o11[t] = (base + y1i * FW + x1i) * C_CH;
        s_w00[t] = wv * hy * hx;
        s_w01[t] = wv * hy * lx;
        s_w10[t] = wv * ly * hx;
        s_w11[t] = wv * ly * lx;
    }
    __syncthreads();

    // ---- phase 2: lane = 8 channels (uint4 of halves), warp sweeps this block's bins ----
    const int warp = t >> 5;
    const int lane = t & 31;
    const int c8   = lane * 8;                     // channel base
    const __half* __restrict__ ftc = g_fth + c8;

    const int b0 = blockIdx.y * 25;                // bins [b0, b0+nb)
    const int nb = blockIdx.y ? 24 : 25;

    for (int ib = warp; ib < nb; ib += 8) {
        const int bin = b0 + ib;
        const int by = bin / 7;
        const int bx = bin - by * 7;
        const int s0 = by * 28 + bx * 2;

        float acc[8];
#pragma unroll
        for (int q = 0; q < 8; ++q) acc[q] = 0.0f;

#pragma unroll
        for (int j = 0; j < 4; ++j) {
            const int si = s0 + ((j >> 1) * 14) + (j & 1);
            const float w0 = s_w00[si];
            const float w1 = s_w01[si];
            const float w2 = s_w10[si];
            const float w3 = s_w11[si];
            const uint4 u0 = __ldg((const uint4*)(ftc + s_o00[si]));
            const uint4 u1 = __ldg((const uint4*)(ftc + s_o01[si]));
            const uint4 u2 = __ldg((const uint4*)(ftc + s_o10[si]));
            const uint4 u3 = __ldg((const uint4*)(ftc + s_o11[si]));
            acc8(acc, u0, w0);
            acc8(acc, u1, w1);
            acc8(acc, u2, w2);
            acc8(acc, u3, w3);
        }
#pragma unroll
        for (int q = 0; q < 8; ++q) acc[q] *= 0.25f;

        float* sp = &s_out[ib * SOUT_LD + c8];
        *(float4*)(sp)     = make_float4(acc[0], acc[1], acc[2], acc[3]);
        *(float4*)(sp + 4) = make_float4(acc[4], acc[5], acc[6], acc[7]);
    }
    __syncthreads();

    // ---- flush: coalesced stores out[r][cc][b0..b0+nb) ----
    float* op = out + (size_t)r * C_CH * 49 + b0;
    for (int cc = warp; cc < C_CH; cc += 8)
        for (int k = lane; k < nb; k += 32)
            op[cc * 49 + k] = s_out[k * SOUT_LD + cc];
}

extern "C" void kernel_launch(void* const* d_in, const int* in_sizes, int n_in,
                              void* d_out, int out_size)
{
    const float* feat  = (const float*)d_in[0];
    const float* rois  = (const float*)d_in[1];
    const float* masks = (const float*)d_in[2];
    float* out = (float*)d_out;

    const int R = in_sizes[1] / 5;   // 512

    dim3 tgrid(PIX / 32, C_CH / 64, NIMG);   // 1250 x 4 x 2
    dim3 tblk(32, 8);
    transpose_kernel<<<tgrid, tblk>>>(feat);

    dim3 rgrid(R, 2);
    roialign_kernel<<<rgrid, 256>>>(rois, masks, out);
}